// round 1
// baseline (speedup 1.0000x reference)
#include <cuda_runtime.h>
#include <math.h>

#define NND 100000
#define D 128
#define NELEM (NND*D)

// Scratch (allocation-free): two ping-pong feature buffers + LN reduction scalars.
__device__ float  g_buf0[NELEM];
__device__ float  g_buf1[NELEM];
__device__ double g_sum[3];
__device__ double g_sumsq[3];

#define PACK2(d, f)  asm("mov.b64 %0, {%1, %1};" : "=l"(d) : "f"(f))
#define UNPACK2(lo, hi, d) asm("mov.b64 {%0, %1}, %2;" : "=f"(lo), "=f"(hi) : "l"(d))
#define FMA2(d, a, b) asm("fma.rn.f32x2 %0, %1, %2, %3;" : "=l"(d) : "l"(a), "l"(b), "l"(d))

// h = (1+eps)*node ; also zero the LN accumulators for this replay.
__global__ void k_init(const float* __restrict__ node, const float* __restrict__ eps_p,
                       float* __restrict__ h) {
    long long i = blockIdx.x * (long long)blockDim.x + threadIdx.x;
    if (i == 0) {
        #pragma unroll
        for (int j = 0; j < 3; ++j) { g_sum[j] = 0.0; g_sumsq[j] = 0.0; }
    }
    if (i < NELEM/4) {
        float s = 1.0f + eps_p[0];
        float4 v = __ldg((const float4*)node + i);
        v.x *= s; v.y *= s; v.z *= s; v.w *= s;
        ((float4*)h)[i] = v;
    }
}

// One warp per edge: gather node[src] row (32 x float4), vector-red into h[dst].
__global__ void k_scatter(const float* __restrict__ node, const int* __restrict__ ei,
                          float* __restrict__ h, int E) {
    long long gid = blockIdx.x * (long long)blockDim.x + threadIdx.x;
    int e    = (int)(gid >> 5);
    int lane = (int)(gid & 31);
    if (e >= E) return;
    int src = __ldg(ei + e);
    int dst = __ldg(ei + E + e);
    float4 v = __ldg((const float4*)node + (long long)src * 32 + lane);
    float* d = h + (long long)dst * D + lane * 4;
    asm volatile("red.global.add.v4.f32 [%0], {%1,%2,%3,%4};"
                 :: "l"(d), "f"(v.x), "f"(v.y), "f"(v.z), "f"(v.w) : "memory");
}

// Y = op(A) @ W + bias, where op is identity (APPLY=false) or
// relu(graph_layernorm(A)) using the sums at sidx_in (APPLY=true).
// Also accumulates sum/sumsq of Y into g_sum/g_sumsq[sidx_out].
// Tile: 128 rows x 128 cols per block, 256 threads, 8x8 micro-tile per thread,
// accumulation in packed f32x2 (FFMA2) pairs along the row dimension.
template<bool APPLY>
__global__ void __launch_bounds__(256)
k_gemm(const float* __restrict__ A, const float* __restrict__ W,
       const float* __restrict__ bias,
       const float* __restrict__ lnw, const float* __restrict__ lnb,
       int sidx_in, int sidx_out,
       float* __restrict__ Y, int M)
{
    __shared__ float As[16][132];   // padded: conflict-free transposed stores
    __shared__ float Bs[16][128];
    __shared__ float s_bias[128];
    __shared__ float s_lnw[128];
    __shared__ float s_lnb[128];

    const int t  = threadIdx.x;
    const int tx = t & 15;
    const int ty = t >> 4;
    const int row0 = blockIdx.x * 128;

    if (t < 128) {
        s_bias[t] = bias[t];
        if (APPLY) { s_lnw[t] = lnw[t]; s_lnb[t] = lnb[t]; }
    }
    float mu = 0.f, inv = 0.f;
    if (APPLY) {
        double m = g_sum[sidx_in] * (1.0 / (double)NELEM);
        double v = g_sumsq[sidx_in] * (1.0 / (double)NELEM) - m * m;
        if (v < 0.0) v = 0.0;
        mu  = (float)m;
        inv = 1.0f / (sqrtf((float)v) + 1e-5f);
    }
    __syncthreads();

    unsigned long long acc[4][8];
    #pragma unroll
    for (int i = 0; i < 4; ++i)
        #pragma unroll
        for (int j = 0; j < 8; ++j) acc[i][j] = 0ULL;

    for (int kb = 0; kb < 128; kb += 16) {
        // Load A tile (128 rows x 16 k), LN+ReLU fused, store transposed.
        #pragma unroll
        for (int it = 0; it < 2; ++it) {
            int idx = t + it * 256;          // 0..511 float4 units
            int r   = idx >> 2;              // row in tile
            int c4  = idx & 3;               // which float4 of the 16-wide chunk
            int grow = row0 + r;
            float4 v = make_float4(0.f, 0.f, 0.f, 0.f);
            if (grow < M) v = __ldg((const float4*)(A + (long long)grow * D + kb) + c4);
            if (APPLY) {
                int k0 = kb + c4 * 4;
                v.x = fmaxf((v.x - mu) * inv * s_lnw[k0+0] + s_lnb[k0+0], 0.f);
                v.y = fmaxf((v.y - mu) * inv * s_lnw[k0+1] + s_lnb[k0+1], 0.f);
                v.z = fmaxf((v.z - mu) * inv * s_lnw[k0+2] + s_lnb[k0+2], 0.f);
                v.w = fmaxf((v.w - mu) * inv * s_lnw[k0+3] + s_lnb[k0+3], 0.f);
            }
            As[c4*4+0][r] = v.x;
            As[c4*4+1][r] = v.y;
            As[c4*4+2][r] = v.z;
            As[c4*4+3][r] = v.w;
        }
        // Load B tile (16 k x 128 cols).
        #pragma unroll
        for (int it = 0; it < 2; ++it) {
            int idx = t + it * 256;
            int kr  = idx >> 5;
            int c4  = idx & 31;
            float4 v = __ldg((const float4*)(W + (long long)(kb + kr) * D) + c4);
            *((float4*)&Bs[kr][0] + c4) = v;
        }
        __syncthreads();

        #pragma unroll
        for (int k = 0; k < 16; ++k) {
            // 8 consecutive A rows for this thread = 4 packed f32x2 pairs.
            const unsigned long long* ap = (const unsigned long long*)&As[k][ty * 8];
            unsigned long long a0 = ap[0], a1 = ap[1], a2 = ap[2], a3 = ap[3];
            // 8 B cols split as [tx*4 .. +3] and [64+tx*4 .. +3] (bank-friendly).
            float4 bA = *(const float4*)&Bs[k][tx * 4];
            float4 bB = *(const float4*)&Bs[k][64 + tx * 4];
            unsigned long long bd[8];
            PACK2(bd[0], bA.x); PACK2(bd[1], bA.y); PACK2(bd[2], bA.z); PACK2(bd[3], bA.w);
            PACK2(bd[4], bB.x); PACK2(bd[5], bB.y); PACK2(bd[6], bB.z); PACK2(bd[7], bB.w);
            #pragma unroll
            for (int j = 0; j < 8; ++j) {
                FMA2(acc[0][j], a0, bd[j]);
                FMA2(acc[1][j], a1, bd[j]);
                FMA2(acc[2][j], a2, bd[j]);
                FMA2(acc[3][j], a3, bd[j]);
            }
        }
        __syncthreads();
    }

    // Epilogue: bias, store, and partial sum / sumsq for the next graph-LN.
    float lsum = 0.f, lsq = 0.f;
    #pragma unroll
    for (int ri = 0; ri < 4; ++ri) {
        float lo[8], hi[8];
        #pragma unroll
        for (int j = 0; j < 8; ++j) UNPACK2(lo[j], hi[j], acc[ri][j]);
        #pragma unroll
        for (int p = 0; p < 2; ++p) {
            int grow = row0 + ty * 8 + ri * 2 + p;
            if (grow < M) {
                float c[8];
                #pragma unroll
                for (int j = 0; j < 8; ++j) {
                    int col = (j < 4) ? (tx * 4 + j) : (64 + tx * 4 + j - 4);
                    float val = (p == 0 ? lo[j] : hi[j]) + s_bias[col];
                    c[j] = val;
                    lsum += val;
                    lsq  += val * val;
                }
                *(float4*)(Y + (long long)grow * D + tx * 4)      = make_float4(c[0], c[1], c[2], c[3]);
                *(float4*)(Y + (long long)grow * D + 64 + tx * 4) = make_float4(c[4], c[5], c[6], c[7]);
            }
        }
    }
    #pragma unroll
    for (int o = 16; o > 0; o >>= 1) {
        lsum += __shfl_down_sync(0xffffffffu, lsum, o);
        lsq  += __shfl_down_sync(0xffffffffu, lsq, o);
    }
    if ((t & 31) == 0) {
        atomicAdd(&g_sum[sidx_out],   (double)lsum);
        atomicAdd(&g_sumsq[sidx_out], (double)lsq);
    }
}

// out = relu(graph_layernorm(Y)) with sums at index 2.
__global__ void k_apply_out(const float* __restrict__ Y, const float* __restrict__ w,
                            const float* __restrict__ b, float* __restrict__ out) {
    long long i = blockIdx.x * (long long)blockDim.x + threadIdx.x;
    if (i >= NELEM/4) return;
    double m = g_sum[2] * (1.0 / (double)NELEM);
    double v = g_sumsq[2] * (1.0 / (double)NELEM) - m * m;
    if (v < 0.0) v = 0.0;
    float mu  = (float)m;
    float inv = 1.0f / (sqrtf((float)v) + 1e-5f);
    int k = ((int)i * 4) & 127;
    float4 val = __ldg((const float4*)Y + i);
    float4 o;
    o.x = fmaxf((val.x - mu) * inv * __ldg(w + k + 0) + __ldg(b + k + 0), 0.f);
    o.y = fmaxf((val.y - mu) * inv * __ldg(w + k + 1) + __ldg(b + k + 1), 0.f);
    o.z = fmaxf((val.z - mu) * inv * __ldg(w + k + 2) + __ldg(b + k + 2), 0.f);
    o.w = fmaxf((val.w - mu) * inv * __ldg(w + k + 3) + __ldg(b + k + 3), 0.f);
    ((float4*)out)[i] = o;
}

extern "C" void kernel_launch(void* const* d_in, const int* in_sizes, int n_in,
                              void* d_out, int out_size) {
    const float* node = (const float*)d_in[0];
    const int*   ei   = (const int*)d_in[1];
    // d_in[2] edge_attr, d_in[3] batch_ptr: unused by the math
    const float* eps  = (const float*)d_in[4];
    const float* W1   = (const float*)d_in[5];
    const float* b1   = (const float*)d_in[6];
    const float* ln1w = (const float*)d_in[7];
    const float* ln1b = (const float*)d_in[8];
    const float* W2   = (const float*)d_in[9];
    const float* b2   = (const float*)d_in[10];
    const float* ln2w = (const float*)d_in[11];
    const float* ln2b = (const float*)d_in[12];
    const float* W3   = (const float*)d_in[13];
    const float* b3   = (const float*)d_in[14];
    const float* lnow = (const float*)d_in[15];
    const float* lnob = (const float*)d_in[16];

    int E = in_sizes[1] / 2;

    void *p0, *p1;
    cudaGetSymbolAddress(&p0, g_buf0);
    cudaGetSymbolAddress(&p1, g_buf1);
    float* buf0 = (float*)p0;
    float* buf1 = (float*)p1;

    int nb_elem = (NELEM/4 + 255) / 256;
    k_init<<<nb_elem, 256>>>(node, eps, buf0);

    long long sthreads = (long long)E * 32;
    int sblocks = (int)((sthreads + 255) / 256);
    k_scatter<<<sblocks, 256>>>(node, ei, buf0, E);

    int gblocks = (NND + 127) / 128;
    k_gemm<false><<<gblocks, 256>>>(buf0, W1, b1, nullptr, nullptr, 0, 0, buf1, NND);
    k_gemm<true> <<<gblocks, 256>>>(buf1, W2, b2, ln1w, ln1b, 0, 1, buf0, NND);
    k_gemm<true> <<<gblocks, 256>>>(buf0, W3, b3, ln2w, ln2b, 1, 2, buf1, NND);

    k_apply_out<<<nb_elem, 256>>>(buf1, lnow, lnob, (float*)d_out);
}